// round 1
// baseline (speedup 1.0000x reference)
#include <cuda_runtime.h>
#include <math.h>

// Problem constants
#define B_DIM 8
#define C_DIM 256
#define H_DIM 128
#define W_DIM 128
#define HW    (H_DIM * W_DIM)          // 16384
#define QK_SCALE 0.0625f               // 1/sqrt(256)

// Scratch q/k/v in [token, channel] layout, token = b*HW + h*W + w
__device__ float g_q[B_DIM * HW * C_DIM];
__device__ float g_k[B_DIM * HW * C_DIM];
__device__ float g_v[B_DIM * HW * C_DIM];

// ---------------------------------------------------------------------------
// Kernel 1: fused QKV projection.
// a is [B, C, H, W]  (token vector a[b, :, h, w] strided by HW)
// q/k/v out as [token, C] row-major. Scale folded into q.
// Block: 64 tokens x 64 outputs x 3 matrices, BK=16, 256 threads (16x16),
// thread tile 4 tokens x 4 outputs per matrix.
// ---------------------------------------------------------------------------
__global__ __launch_bounds__(256)
void qkv_kernel(const float* __restrict__ a,
                const float* __restrict__ wq, const float* __restrict__ bq,
                const float* __restrict__ wk, const float* __restrict__ bk,
                const float* __restrict__ wv, const float* __restrict__ bv)
{
    __shared__ float As[16][64];        // [k][token]
    __shared__ float Ws[3][16][64];     // [mat][k][out]  (transposed on load)

    const int tid = threadIdx.x;
    const int tx = tid & 15;            // token sub-tile
    const int ty = tid >> 4;            // output sub-tile

    const int tt  = blockIdx.x;         // 0..2047
    const int b   = tt >> 8;            // 256 token-tiles per batch
    const int hw0 = (tt & 255) << 6;    // token tile start within batch
    const int o0  = blockIdx.y << 6;    // output tile start

    const float* wsrc0 = wq;
    const float* wsrc1 = wk;
    const float* wsrc2 = wv;

    float acc[3][4][4];
    #pragma unroll
    for (int m = 0; m < 3; ++m)
        #pragma unroll
        for (int i = 0; i < 4; ++i)
            #pragma unroll
            for (int j = 0; j < 4; ++j)
                acc[m][i][j] = 0.0f;

    const float* abase = a + (size_t)b * C_DIM * HW + hw0;

    const int ar  = tid >> 4;           // 0..15  (k row for A load)
    const int ac4 = tid & 15;           // 0..15  (token float4 chunk)
    const int wo  = tid >> 2;           // 0..63  (output row for W load)
    const int wc4 = tid & 3;            // 0..3   (k float4 chunk)

    for (int kt = 0; kt < 16; ++kt) {
        const int k0 = kt << 4;
        __syncthreads();
        // Load A tile [16 k x 64 tokens], coalesced along tokens
        {
            float4 v4 = *(const float4*)(abase + (size_t)(k0 + ar) * HW + ac4 * 4);
            *(float4*)&As[ar][ac4 * 4] = v4;
        }
        // Load W tiles transposed: Ws[m][k][o]
        {
            float4 v4;
            v4 = *(const float4*)(wsrc0 + (o0 + wo) * C_DIM + k0 + wc4 * 4);
            Ws[0][wc4 * 4 + 0][wo] = v4.x; Ws[0][wc4 * 4 + 1][wo] = v4.y;
            Ws[0][wc4 * 4 + 2][wo] = v4.z; Ws[0][wc4 * 4 + 3][wo] = v4.w;
            v4 = *(const float4*)(wsrc1 + (o0 + wo) * C_DIM + k0 + wc4 * 4);
            Ws[1][wc4 * 4 + 0][wo] = v4.x; Ws[1][wc4 * 4 + 1][wo] = v4.y;
            Ws[1][wc4 * 4 + 2][wo] = v4.z; Ws[1][wc4 * 4 + 3][wo] = v4.w;
            v4 = *(const float4*)(wsrc2 + (o0 + wo) * C_DIM + k0 + wc4 * 4);
            Ws[2][wc4 * 4 + 0][wo] = v4.x; Ws[2][wc4 * 4 + 1][wo] = v4.y;
            Ws[2][wc4 * 4 + 2][wo] = v4.z; Ws[2][wc4 * 4 + 3][wo] = v4.w;
        }
        __syncthreads();

        #pragma unroll
        for (int kk = 0; kk < 16; ++kk) {
            float4 av = *(float4*)&As[kk][tx * 4];
            float am[4] = {av.x, av.y, av.z, av.w};
            #pragma unroll
            for (int m = 0; m < 3; ++m) {
                float4 w4 = *(float4*)&Ws[m][kk][ty * 4];
                float wm[4] = {w4.x, w4.y, w4.z, w4.w};
                #pragma unroll
                for (int i = 0; i < 4; ++i)
                    #pragma unroll
                    for (int j = 0; j < 4; ++j)
                        acc[m][i][j] = fmaf(am[i], wm[j], acc[m][i][j]);
            }
        }
    }

    // Epilogue: add bias, scale q, store [token, C]
    const size_t tokbase = (size_t)b * HW + hw0;
    float bias0[4], bias1[4], bias2[4];
    #pragma unroll
    for (int j = 0; j < 4; ++j) {
        bias0[j] = bq[o0 + ty * 4 + j];
        bias1[j] = bk[o0 + ty * 4 + j];
        bias2[j] = bv[o0 + ty * 4 + j];
    }
    #pragma unroll
    for (int i = 0; i < 4; ++i) {
        const size_t row = (tokbase + tx * 4 + i) * C_DIM + o0 + ty * 4;
        float4 r4;
        r4.x = (acc[0][i][0] + bias0[0]) * QK_SCALE;
        r4.y = (acc[0][i][1] + bias0[1]) * QK_SCALE;
        r4.z = (acc[0][i][2] + bias0[2]) * QK_SCALE;
        r4.w = (acc[0][i][3] + bias0[3]) * QK_SCALE;
        *(float4*)&g_q[row] = r4;
        r4.x = acc[1][i][0] + bias1[0];
        r4.y = acc[1][i][1] + bias1[1];
        r4.z = acc[1][i][2] + bias1[2];
        r4.w = acc[1][i][3] + bias1[3];
        *(float4*)&g_k[row] = r4;
        r4.x = acc[2][i][0] + bias2[0];
        r4.y = acc[2][i][1] + bias2[1];
        r4.z = acc[2][i][2] + bias2[2];
        r4.w = acc[2][i][3] + bias2[3];
        *(float4*)&g_v[row] = r4;
    }
}

// ---------------------------------------------------------------------------
// Kernel 2: per-scanline attention + residual epilogue.
// One block per (b, h). 256 threads (16x16).
// Phase S: S = Qs Ks^T (scale already in q), 8x8 per thread, BK=32,
//          k-major transposed smem tiles for conflict-free float4 frags.
// Softmax: per-row max/sum via half-warp shuffles (row owned by 16 lanes).
// Phase O: O = P V with c-tiles of 64, 8x4 per thread, P float4 over k.
// Epilogue: out = a + O * Wp, staged via smem for coalesced NCHW writes.
// ---------------------------------------------------------------------------
#define QT_STRIDE 136    // 32 x 136 each for QtT / KtT
#define PS_STRIDE 132    // 128 x 132
#define VT_STRIDE 68     // 128 x 68
#define ATTN_SMEM_FLOATS (128 * PS_STRIDE + 128 * VT_STRIDE)   // 25600
#define ATTN_SMEM_BYTES  (ATTN_SMEM_FLOATS * 4)                // 102400

__global__ __launch_bounds__(256)
void attn_kernel(const float* __restrict__ a,
                 const float* __restrict__ Wp,
                 float* __restrict__ out)
{
    extern __shared__ float sm[];
    float* QtT = sm;                       // [32][136]   (phase S only)
    float* KtT = sm + 32 * QT_STRIDE;      // [32][136]
    float* Ps  = sm;                       // [128][132]  (overlays QtT/KtT)
    float* Vt  = sm + 128 * PS_STRIDE;     // [128][68]

    const int tid = threadIdx.x;
    const int tx = tid & 15;
    const int ty = tid >> 4;

    const int bh = blockIdx.x;             // 0..1023
    const int b  = bh >> 7;
    const int h  = bh & 127;

    const size_t qbase = (size_t)bh * (W_DIM * C_DIM);
    const float* qp = g_q + qbase;
    const float* kp = g_k + qbase;
    const float* vp = g_v + qbase;

    float s[8][8];
    #pragma unroll
    for (int i = 0; i < 8; ++i)
        #pragma unroll
        for (int j = 0; j < 8; ++j)
            s[i][j] = 0.0f;

    // ---- Phase S: S = Q K^T ----
    for (int kt = 0; kt < 8; ++kt) {
        const int k0 = kt << 5;
        __syncthreads();
        #pragma unroll
        for (int it = 0; it < 4; ++it) {
            const int item = it * 256 + tid;
            const int tok = item >> 3;
            const int c4  = item & 7;
            float4 qv = *(const float4*)(qp + tok * C_DIM + k0 + c4 * 4);
            QtT[(c4 * 4 + 0) * QT_STRIDE + tok] = qv.x;
            QtT[(c4 * 4 + 1) * QT_STRIDE + tok] = qv.y;
            QtT[(c4 * 4 + 2) * QT_STRIDE + tok] = qv.z;
            QtT[(c4 * 4 + 3) * QT_STRIDE + tok] = qv.w;
            float4 kv = *(const float4*)(kp + tok * C_DIM + k0 + c4 * 4);
            KtT[(c4 * 4 + 0) * QT_STRIDE + tok] = kv.x;
            KtT[(c4 * 4 + 1) * QT_STRIDE + tok] = kv.y;
            KtT[(c4 * 4 + 2) * QT_STRIDE + tok] = kv.z;
            KtT[(c4 * 4 + 3) * QT_STRIDE + tok] = kv.w;
        }
        __syncthreads();

        #pragma unroll
        for (int kk = 0; kk < 32; ++kk) {
            const float* qr = &QtT[kk * QT_STRIDE + ty * 8];
            float4 q0 = *(const float4*)qr;
            float4 q1 = *(const float4*)(qr + 4);
            const float* kr = &KtT[kk * QT_STRIDE + tx * 8];
            float4 k0v = *(const float4*)kr;
            float4 k1v = *(const float4*)(kr + 4);
            float qf[8] = {q0.x, q0.y, q0.z, q0.w, q1.x, q1.y, q1.z, q1.w};
            float kf[8] = {k0v.x, k0v.y, k0v.z, k0v.w, k1v.x, k1v.y, k1v.z, k1v.w};
            #pragma unroll
            for (int i = 0; i < 8; ++i)
                #pragma unroll
                for (int j = 0; j < 8; ++j)
                    s[i][j] = fmaf(qf[i], kf[j], s[i][j]);
        }
    }
    __syncthreads();   // all QtT/KtT reads done before Ps overlay writes

    // ---- Softmax along each row; rows owned by 16 lanes of a half-warp ----
    #pragma unroll
    for (int i = 0; i < 8; ++i) {
        float mx = s[i][0];
        #pragma unroll
        for (int j = 1; j < 8; ++j) mx = fmaxf(mx, s[i][j]);
        #pragma unroll
        for (int off = 8; off >= 1; off >>= 1)
            mx = fmaxf(mx, __shfl_xor_sync(0xffffffffu, mx, off));
        float sum = 0.0f;
        #pragma unroll
        for (int j = 0; j < 8; ++j) {
            s[i][j] = __expf(s[i][j] - mx);
            sum += s[i][j];
        }
        #pragma unroll
        for (int off = 8; off >= 1; off >>= 1)
            sum += __shfl_xor_sync(0xffffffffu, sum, off);
        const float inv = 1.0f / sum;
        const int r = ty * 8 + i;
        float4 p0 = make_float4(s[i][0] * inv, s[i][1] * inv, s[i][2] * inv, s[i][3] * inv);
        float4 p1 = make_float4(s[i][4] * inv, s[i][5] * inv, s[i][6] * inv, s[i][7] * inv);
        *(float4*)&Ps[r * PS_STRIDE + tx * 8]     = p0;
        *(float4*)&Ps[r * PS_STRIDE + tx * 8 + 4] = p1;
    }
    __syncthreads();

    const float wpv = Wp[0];

    // ---- Phase O: O = P V, c-tiles of 64 ----
    for (int ct = 0; ct < 4; ++ct) {
        const int c0 = ct << 6;
        __syncthreads();   // prior staged-O reads of Vt complete
        #pragma unroll
        for (int it = 0; it < 8; ++it) {
            const int item = it * 256 + tid;
            const int tok = item >> 4;
            const int c4  = item & 15;
            float4 vv = *(const float4*)(vp + tok * C_DIM + c0 + c4 * 4);
            *(float4*)&Vt[tok * VT_STRIDE + c4 * 4] = vv;
        }
        __syncthreads();

        float oacc[8][4];
        #pragma unroll
        for (int i = 0; i < 8; ++i)
            #pragma unroll
            for (int j = 0; j < 4; ++j)
                oacc[i][j] = 0.0f;

        #pragma unroll 4
        for (int kt2 = 0; kt2 < 32; ++kt2) {
            const int kk = kt2 << 2;
            float4 pv[8];
            #pragma unroll
            for (int i = 0; i < 8; ++i)
                pv[i] = *(const float4*)&Ps[(ty * 8 + i) * PS_STRIDE + kk];
            #pragma unroll
            for (int u = 0; u < 4; ++u) {
                float4 vv = *(const float4*)&Vt[(kk + u) * VT_STRIDE + tx * 4];
                #pragma unroll
                for (int i = 0; i < 8; ++i) {
                    const float p = (u == 0) ? pv[i].x : (u == 1) ? pv[i].y
                                  : (u == 2) ? pv[i].z : pv[i].w;
                    oacc[i][0] = fmaf(p, vv.x, oacc[i][0]);
                    oacc[i][1] = fmaf(p, vv.y, oacc[i][1]);
                    oacc[i][2] = fmaf(p, vv.z, oacc[i][2]);
                    oacc[i][3] = fmaf(p, vv.w, oacc[i][3]);
                }
            }
        }
        __syncthreads();
        // Stage O tile into Vt (V no longer needed)
        #pragma unroll
        for (int i = 0; i < 8; ++i) {
            float4 o4 = make_float4(oacc[i][0], oacc[i][1], oacc[i][2], oacc[i][3]);
            *(float4*)&Vt[(ty * 8 + i) * VT_STRIDE + tx * 4] = o4;
        }
        __syncthreads();
        // Coalesced NCHW write: out[b, c0+ci, h, w] = a + o*Wp
        #pragma unroll
        for (int it = 0; it < 32; ++it) {
            const int item = it * 256 + tid;
            const int ci = item >> 7;
            const int w  = item & 127;
            const size_t g = ((size_t)(b * C_DIM + c0 + ci) * H_DIM + h) * W_DIM + w;
            out[g] = a[g] + Vt[w * VT_STRIDE + ci] * wpv;
        }
    }
}

// ---------------------------------------------------------------------------
extern "C" void kernel_launch(void* const* d_in, const int* in_sizes, int n_in,
                              void* d_out, int out_size)
{
    const float* a  = (const float*)d_in[0];
    const float* wq = (const float*)d_in[1];
    const float* bq = (const float*)d_in[2];
    const float* wk = (const float*)d_in[3];
    const float* bk = (const float*)d_in[4];
    const float* wv = (const float*)d_in[5];
    const float* bv = (const float*)d_in[6];
    const float* Wp = (const float*)d_in[7];
    float* out = (float*)d_out;

    (void)in_sizes; (void)n_in; (void)out_size;

    // Opt in to >48KB dynamic smem for the attention kernel (idempotent).
    cudaFuncSetAttribute(attn_kernel,
                         cudaFuncAttributeMaxDynamicSharedMemorySize,
                         ATTN_SMEM_BYTES);

    dim3 grid1(2048, 4);
    qkv_kernel<<<grid1, 256>>>(a, wq, bq, wk, bk, wv, bv);

    attn_kernel<<<1024, 256, ATTN_SMEM_BYTES>>>(a, Wp, out);
}

// round 3
// speedup vs baseline: 1.7485x; 1.7485x over previous
#include <cuda_runtime.h>
#include <cuda_bf16.h>
#include <stdint.h>
#include <math.h>

// Problem constants
#define B_DIM 8
#define C_DIM 256
#define H_DIM 128
#define W_DIM 128
#define HW    (H_DIM * W_DIM)          // 16384
#define NTOK  (B_DIM * HW)             // 131072
#define QK_SCALE 0.0625f               // 1/sqrt(256)

// Scratch q/k/v in [token][channel] layout, token = b*HW + h*W + w
__device__ float g_q[NTOK * C_DIM];
__device__ float g_k[NTOK * C_DIM];
__device__ float g_v[NTOK * C_DIM];

// X in c-major bf16 split: [c][token]
__device__ __nv_bfloat16 g_xhi[C_DIM * NTOK];
__device__ __nv_bfloat16 g_xlo[C_DIM * NTOK];

// Weights split: [mat][o][c]  (o = output/N, c = input/K)
__device__ __nv_bfloat16 g_whi[3 * C_DIM * C_DIM];
__device__ __nv_bfloat16 g_wlo[3 * C_DIM * C_DIM];

// ===========================================================================
// Small helpers
// ===========================================================================
__device__ __forceinline__ uint32_t smem_u32(const void* p) {
    uint32_t a;
    asm("{ .reg .u64 t; cvta.to.shared.u64 t, %1; cvt.u32.u64 %0, t; }" : "=r"(a) : "l"(p));
    return a;
}
__device__ __forceinline__ void cp16(uint32_t dst, const void* src) {
    asm volatile("cp.async.cg.shared.global [%0], [%1], 16;" :: "r"(dst), "l"(src));
}
__device__ __forceinline__ void cp_commit() { asm volatile("cp.async.commit_group;" ::: "memory"); }
__device__ __forceinline__ void cp_wait1()  { asm volatile("cp.async.wait_group 1;" ::: "memory"); }
__device__ __forceinline__ void cp_wait0()  { asm volatile("cp.async.wait_group 0;" ::: "memory"); }

__device__ __forceinline__ void ldm_x4(uint32_t& r0, uint32_t& r1, uint32_t& r2, uint32_t& r3, uint32_t addr) {
    asm volatile("ldmatrix.sync.aligned.m8n8.x4.shared.b16 {%0,%1,%2,%3}, [%4];"
                 : "=r"(r0), "=r"(r1), "=r"(r2), "=r"(r3) : "r"(addr));
}
__device__ __forceinline__ void ldm_x4_t(uint32_t& r0, uint32_t& r1, uint32_t& r2, uint32_t& r3, uint32_t addr) {
    asm volatile("ldmatrix.sync.aligned.m8n8.x4.trans.shared.b16 {%0,%1,%2,%3}, [%4];"
                 : "=r"(r0), "=r"(r1), "=r"(r2), "=r"(r3) : "r"(addr));
}
__device__ __forceinline__ void mma16816(float& c0, float& c1, float& c2, float& c3,
                                         uint32_t a0, uint32_t a1, uint32_t a2, uint32_t a3,
                                         uint32_t b0, uint32_t b1) {
    asm volatile("mma.sync.aligned.m16n8k16.row.col.f32.bf16.bf16.f32 "
                 "{%0,%1,%2,%3},{%4,%5,%6,%7},{%8,%9},{%0,%1,%2,%3};"
                 : "+f"(c0), "+f"(c1), "+f"(c2), "+f"(c3)
                 : "r"(a0), "r"(a1), "r"(a2), "r"(a3), "r"(b0), "r"(b1));
}

// ===========================================================================
// Weight conversion: fp32 -> bf16 hi/lo split, [mat][o][c]
// ===========================================================================
__global__ __launch_bounds__(256)
void wconvert(const float* __restrict__ wq, const float* __restrict__ wk,
              const float* __restrict__ wv)
{
    int idx = blockIdx.x * 256 + threadIdx.x;       // 0..196607
    int mat = idx >> 16;
    int r   = idx & 65535;
    const float* src = (mat == 0) ? wq : (mat == 1) ? wk : wv;
    float v = src[r];
    __nv_bfloat16 hi = __float2bfloat16(v);
    __nv_bfloat16 lo = __float2bfloat16(v - __bfloat162float(hi));
    g_whi[idx] = hi;
    g_wlo[idx] = lo;
}

// ===========================================================================
// X conversion: a NCHW fp32 -> g_xhi/g_xlo [c][token] bf16 (pure elementwise,
// fully coalesced both sides; no transpose needed since c-major preserved)
// ===========================================================================
__global__ __launch_bounds__(256)
void xconvert(const float* __restrict__ a)
{
    int idx4 = blockIdx.x * 256 + threadIdx.x;      // 8388608 float4s
    int b    = idx4 >> 20;                          // 2^20 float4 per batch
    int rem  = idx4 & 1048575;
    int c    = rem >> 12;                           // 2^12 float4 per (b,c)
    int hw4  = rem & 4095;
    float4 v = *(const float4*)(a + (size_t)idx4 * 4);
    size_t o = (size_t)c * NTOK + (size_t)b * HW + (size_t)hw4 * 4;

    float hx = __bfloat162float(__float2bfloat16(v.x));
    float hy = __bfloat162float(__float2bfloat16(v.y));
    float hz = __bfloat162float(__float2bfloat16(v.z));
    float hw = __bfloat162float(__float2bfloat16(v.w));
    __nv_bfloat162* ph = (__nv_bfloat162*)(g_xhi + o);
    ph[0] = __floats2bfloat162_rn(v.x, v.y);
    ph[1] = __floats2bfloat162_rn(v.z, v.w);
    __nv_bfloat162* pl = (__nv_bfloat162*)(g_xlo + o);
    pl[0] = __floats2bfloat162_rn(v.x - hx, v.y - hy);
    pl[1] = __floats2bfloat162_rn(v.z - hz, v.w - hw);
}

// ===========================================================================
// QKV GEMM via mma.sync bf16 (3-pass hi/lo split as K=768).
// Grid: (6, 1024). blockIdx.x = mat*2 + halfN; blockIdx.y = token tile (128).
// CTA: 128 tokens x 128 outputs. 8 warps as 4(M) x 2(N): warp = 32 x 64.
// A smem: [k=64][m=128] bf16 (col-major M), ldmatrix.trans.
// B smem: [n=128][k=64] bf16 (col-major K=B-col), plain ldmatrix.
// XOR-swizzle on 16B chunks: phys = c16 ^ (row & 7). cp.async double buffer.
// ===========================================================================
#define QKV_SMEM 65536

__device__ __forceinline__ void load_tileA(uint32_t dstBase, const __nv_bfloat16* src, int tid)
{
    // 64 rows(k) x 16 chunks of 16B
    #pragma unroll
    for (int it = 0; it < 4; ++it) {
        int id = it * 256 + tid;
        int row = id >> 4, c16 = id & 15;
        uint32_t dst = dstBase + row * 256 + ((c16 ^ (row & 7)) << 4);
        cp16(dst, src + (size_t)row * NTOK + c16 * 8);
    }
}
__device__ __forceinline__ void load_tileB(uint32_t dstBase, const __nv_bfloat16* src, int tid)
{
    // 128 rows(n) x 8 chunks of 16B
    #pragma unroll
    for (int it = 0; it < 4; ++it) {
        int id = it * 256 + tid;
        int row = id >> 3, c16 = id & 7;
        uint32_t dst = dstBase + row * 128 + ((c16 ^ (row & 7)) << 4);
        cp16(dst, src + row * 256 + c16 * 8);
    }
}

__global__ __launch_bounds__(256, 2)
void qkv_mma(const float* __restrict__ bq, const float* __restrict__ bk,
             const float* __restrict__ bv)
{
    extern __shared__ char smem[];
    const uint32_t sb = smem_u32(smem);
    const int tid = threadIdx.x;
    const int lane = tid & 31;
    const int wid = tid >> 5;
    const int wm0 = (wid & 3) * 32;      // warp M origin
    const int wn0 = (wid >> 2) * 64;     // warp N origin

    const int mat  = blockIdx.x >> 1;
    const int half = blockIdx.x & 1;
    const int tok0 = blockIdx.y * 128;

    float acc[2][8][4];
    #pragma unroll
    for (int mt = 0; mt < 2; ++mt)
        #pragma unroll
        for (int n8 = 0; n8 < 8; ++n8)
            #pragma unroll
            for (int e = 0; e < 4; ++e)
                acc[mt][n8][e] = 0.0f;

    // chunk c (0..11): seg = c>>2 selects pass, kin = (c&3)*64
    auto srcA = [&](int c) -> const __nv_bfloat16* {
        int seg = c >> 2, kin = (c & 3) * 64;
        const __nv_bfloat16* x = (seg < 2) ? g_xhi : g_xlo;
        return x + (size_t)kin * NTOK + tok0;
    };
    auto srcB = [&](int c) -> const __nv_bfloat16* {
        int seg = c >> 2, kin = (c & 3) * 64;
        const __nv_bfloat16* w = (seg == 1) ? g_wlo : g_whi;
        return w + mat * 65536 + half * 32768 + kin;
    };

    // Prologue: chunk 0 -> stage 0
    load_tileA(sb, srcA(0), tid);
    load_tileB(sb + 16384, srcB(0), tid);
    cp_commit();

    for (int c = 0; c < 12; ++c) {
        if (c + 1 < 12) {
            uint32_t st = sb + ((c + 1) & 1) * 32768;
            load_tileA(st, srcA(c + 1), tid);
            load_tileB(st + 16384, srcB(c + 1), tid);
            cp_commit();
            cp_wait1();
        } else {
            cp_wait0();
        }
        __syncthreads();

        const uint32_t Ab = sb + (c & 1) * 32768;
        const uint32_t Bb = Ab + 16384;

        #pragma unroll
        for (int ks = 0; ks < 4; ++ks) {
            // A fragments (trans): rows = k, cols = m
            uint32_t af[2][4];
            {
                const int arow = ks * 16 + (lane & 7) + ((lane >> 4) << 3);
                #pragma unroll
                for (int mt = 0; mt < 2; ++mt) {
                    int chunk = (wm0 >> 3) + mt * 2 + ((lane >> 3) & 1);
                    uint32_t addr = Ab + arow * 256 + ((chunk ^ (arow & 7)) << 4);
                    ldm_x4_t(af[mt][0], af[mt][1], af[mt][2], af[mt][3], addr);
                }
            }
            // B fragments: rows = n, cols = k
            uint32_t bf[4][4];
            {
                const int rbase = (lane & 7) + ((lane >> 3) & 1) * 8;
                const int c16 = ks * 2 + (lane >> 4);
                #pragma unroll
                for (int ng = 0; ng < 4; ++ng) {
                    int brow = wn0 + ng * 16 + rbase;
                    uint32_t addr = Bb + brow * 128 + (((c16) ^ (brow & 7)) << 4);
                    ldm_x4(bf[ng][0], bf[ng][1], bf[ng][2], bf[ng][3], addr);
                }
            }
            #pragma unroll
            for (int mt = 0; mt < 2; ++mt)
                #pragma unroll
                for (int n8 = 0; n8 < 8; ++n8) {
                    int g = n8 >> 1, p = n8 & 1;
                    mma16816(acc[mt][n8][0], acc[mt][n8][1], acc[mt][n8][2], acc[mt][n8][3],
                             af[mt][0], af[mt][1], af[mt][2], af[mt][3],
                             bf[g][p], bf[g][p + 2]);
                }
        }
        __syncthreads();
    }

    // Epilogue
    const float* bias = (mat == 0) ? bq : (mat == 1) ? bk : bv;
    float* dst = (mat == 0) ? g_q : (mat == 1) ? g_k : g_v;
    const float scale = (mat == 0) ? QK_SCALE : 1.0f;

    const int g = lane >> 2, t = lane & 3;
    float2 b2[8];
    #pragma unroll
    for (int n8 = 0; n8 < 8; ++n8) {
        int o = half * 128 + wn0 + n8 * 8 + t * 2;
        b2[n8].x = bias[o];
        b2[n8].y = bias[o + 1];
    }
    #pragma unroll
    for (int mt = 0; mt < 2; ++mt) {
        int r0 = tok0 + wm0 + mt * 16 + g;
        #pragma unroll
        for (int n8 = 0; n8 < 8; ++n8) {
            int o = half * 128 + wn0 + n8 * 8 + t * 2;
            float2 v0, v1;
            v0.x = (acc[mt][n8][0] + b2[n8].x) * scale;
            v0.y = (acc[mt][n8][1] + b2[n8].y) * scale;
            v1.x = (acc[mt][n8][2] + b2[n8].x) * scale;
            v1.y = (acc[mt][n8][3] + b2[n8].y) * scale;
            *(float2*)(dst + (size_t)r0 * 256 + o) = v0;
            *(float2*)(dst + (size_t)(r0 + 8) * 256 + o) = v1;
        }
    }
}

// ---------------------------------------------------------------------------
// Attention kernel (unchanged from R1 pass; 509us)
// ---------------------------------------------------------------------------
#define QT_STRIDE 136
#define PS_STRIDE 132
#define VT_STRIDE 68
#define ATTN_SMEM_FLOATS (128 * PS_STRIDE + 128 * VT_STRIDE)
#define ATTN_SMEM_BYTES  (ATTN_SMEM_FLOATS * 4)

__global__ __launch_bounds__(256)
void attn_kernel(const float* __restrict__ a,
                 const float* __restrict__ Wp,
                 float* __restrict__ out)
{
    extern __shared__ float sm[];
    float* QtT = sm;
    float* KtT = sm + 32 * QT_STRIDE;
    float* Ps  = sm;
    float* Vt  = sm + 128 * PS_STRIDE;

    const int tid = threadIdx.x;
    const int tx = tid & 15;
    const int ty = tid >> 4;

    const int bh = blockIdx.x;
    const int b  = bh >> 7;
    const int h  = bh & 127;

    const size_t qbase = (size_t)bh * (W_DIM * C_DIM);
    const float* qp = g_q + qbase;
    const float* kp = g_k + qbase;
    const float* vp = g_v + qbase;

    float s[8][8];
    #pragma unroll
    for (int i = 0; i < 8; ++i)
        #pragma unroll
        for (int j = 0; j < 8; ++j)
            s[i][j] = 0.0f;

    for (int kt = 0; kt < 8; ++kt) {
        const int k0 = kt << 5;
        __syncthreads();
        #pragma unroll
        for (int it = 0; it < 4; ++it) {
            const int item = it * 256 + tid;
            const int tok = item >> 3;
            const int c4  = item & 7;
            float4 qv = *(const float4*)(qp + tok * C_DIM + k0 + c4 * 4);
            QtT[(c4 * 4 + 0) * QT_STRIDE + tok] = qv.x;
            QtT[(c4 * 4 + 1) * QT_STRIDE + tok] = qv.y;
            QtT[(c4 * 4 + 2) * QT_STRIDE + tok] = qv.z;
            QtT[(c4 * 4 + 3) * QT_STRIDE + tok] = qv.w;
            float4 kv = *(const float4*)(kp + tok * C_DIM + k0 + c4 * 4);
            KtT[(c4 * 4 + 0) * QT_STRIDE + tok] = kv.x;
            KtT[(c4 * 4 + 1) * QT_STRIDE + tok] = kv.y;
            KtT[(c4 * 4 + 2) * QT_STRIDE + tok] = kv.z;
            KtT[(c4 * 4 + 3) * QT_STRIDE + tok] = kv.w;
        }
        __syncthreads();

        #pragma unroll
        for (int kk = 0; kk < 32; ++kk) {
            const float* qr = &QtT[kk * QT_STRIDE + ty * 8];
            float4 q0 = *(const float4*)qr;
            float4 q1 = *(const float4*)(qr + 4);
            const float* kr = &KtT[kk * QT_STRIDE + tx * 8];
            float4 k0v = *(const float4*)kr;
            float4 k1v = *(const float4*)(kr + 4);
            float qf[8] = {q0.x, q0.y, q0.z, q0.w, q1.x, q1.y, q1.z, q1.w};
            float kf[8] = {k0v.x, k0v.y, k0v.z, k0v.w, k1v.x, k1v.y, k1v.z, k1v.w};
            #pragma unroll
            for (int i = 0; i < 8; ++i)
                #pragma unroll
                for (int j = 0; j < 8; ++j)
                    s[i][j] = fmaf(qf[i], kf[j], s[i][j]);
        }
    }
    __syncthreads();

    #pragma unroll
    for (int i = 0; i < 8; ++i) {
        float mx = s[i][0];
        #pragma unroll
        for (int j = 1; j < 8; ++j) mx = fmaxf(mx, s[i][j]);
        #pragma unroll
        for (int off = 8; off >= 1; off >>= 1)
            mx = fmaxf(mx, __shfl_xor_sync(0xffffffffu, mx, off));
        float sum = 0.0f;
        #pragma unroll
        for (int j = 0; j < 8; ++j) {
            s[i][j] = __expf(s[i][j] - mx);
            sum += s[i][j];
        }
        #pragma unroll
        for (int off = 8; off >= 1; off >>= 1)
            sum += __shfl_xor_sync(0xffffffffu, sum, off);
        const float inv = 1.0f / sum;
        const int r = ty * 8 + i;
        float4 p0 = make_float4(s[i][0] * inv, s[i][1] * inv, s[i][2] * inv, s[i][3] * inv);
        float4 p1 = make_float4(s[i][4] * inv, s[i][5] * inv, s[i][6] * inv, s[i][7] * inv);
        *(float4*)&Ps[r * PS_STRIDE + tx * 8]     = p0;
        *(float4*)&Ps[r * PS_STRIDE + tx * 8 + 4] = p1;
    }
    __syncthreads();

    const float wpv = Wp[0];

    for (int ct = 0; ct < 4; ++ct) {
        const int c0 = ct << 6;
        __syncthreads();
        #pragma unroll
        for (int it = 0; it < 8; ++it) {
            const int item = it * 256 + tid;
            const int tok = item >> 4;
            const int c4  = item & 15;
            float4 vv = *(const float4*)(vp + tok * C_DIM + c0 + c4 * 4);
            *(float4*)&Vt[tok * VT_STRIDE + c4 * 4] = vv;
        }
        __syncthreads();

        float oacc[8][4];
        #pragma unroll
        for (int i = 0; i < 8; ++i)
            #pragma unroll
            for (int j = 0; j < 4; ++j)
                oacc[i][j] = 0.0f;

        #pragma unroll 4
        for (int kt2 = 0; kt2 < 32; ++kt2) {
            const int kk = kt2 << 2;
            float4 pv[8];
            #pragma unroll
            for (int i = 0; i < 8; ++i)
                pv[i] = *(const float4*)&Ps[(ty * 8 + i) * PS_STRIDE + kk];
            #pragma unroll
            for (int u = 0; u < 4; ++u) {
                float4 vv = *(const float4*)&Vt[(kk + u) * VT_STRIDE + tx * 4];
                #pragma unroll
                for (int i = 0; i < 8; ++i) {
                    const float p = (u == 0) ? pv[i].x : (u == 1) ? pv[i].y
                                  : (u == 2) ? pv[i].z : pv[i].w;
                    oacc[i][0] = fmaf(p, vv.x, oacc[i][0]);
                    oacc[i][1] = fmaf(p, vv.y, oacc[i][1]);
                    oacc[i][2] = fmaf(p, vv.z, oacc[i][2]);
                    oacc[i][3] = fmaf(p, vv.w, oacc[i][3]);
                }
            }
        }
        __syncthreads();
        #pragma unroll
        for (int i = 0; i < 8; ++i) {
            float4 o4 = make_float4(oacc[i][0], oacc[i][1], oacc[i][2], oacc[i][3]);
            *(float4*)&Vt[(ty * 8 + i) * VT_STRIDE + tx * 4] = o4;
        }
        __syncthreads();
        #pragma unroll
        for (int it = 0; it < 32; ++it) {
            const int item = it * 256 + tid;
            const int ci = item >> 7;
            const int w  = item & 127;
            const size_t g = ((size_t)(b * C_DIM + c0 + ci) * H_DIM + h) * W_DIM + w;
            out[g] = a[g] + Vt[w * VT_STRIDE + ci] * wpv;
        }
    }
}

// ---------------------------------------------------------------------------
extern "C" void kernel_launch(void* const* d_in, const int* in_sizes, int n_in,
                              void* d_out, int out_size)
{
    const float* a  = (const float*)d_in[0];
    const float* wq = (const float*)d_in[1];
    const float* bq = (const float*)d_in[2];
    const float* wk = (const float*)d_in[3];
    const float* bk = (const float*)d_in[4];
    const float* wv = (const float*)d_in[5];
    const float* bv = (const float*)d_in[6];
    const float* Wp = (const float*)d_in[7];
    float* out = (float*)d_out;

    (void)in_sizes; (void)n_in; (void)out_size;

    cudaFuncSetAttribute(qkv_mma,
                         cudaFuncAttributeMaxDynamicSharedMemorySize, QKV_SMEM);
    cudaFuncSetAttribute(attn_kernel,
                         cudaFuncAttributeMaxDynamicSharedMemorySize, ATTN_SMEM_BYTES);

    wconvert<<<768, 256>>>(wq, wk, wv);
    xconvert<<<32768, 256>>>(a);
    qkv_mma<<<dim3(6, 1024), 256, QKV_SMEM>>>(bq, bk, bv);
    attn_kernel<<<1024, 256, ATTN_SMEM_BYTES>>>(a, Wp, out);
}